// round 16
// baseline (speedup 1.0000x reference)
#include <cuda_runtime.h>
#include <math.h>

#define NX 400
#define NY 400
#define NC (NX*NY)
#define STEPS 300
#define NSTRIP 74
#define NBLK (2*NSTRIP)
#define TPB 320
#define MAXH 6
#define SRC_I 30
#define DET_I 370
#define PI_F 3.14159265358979323846f
#define NSLOT 200                  // 2 columns per 16B slot

typedef unsigned long long u64;

// Persistent device state (no allocations allowed)
__device__ float d_ie[NC];                 // COURANT / eps
__device__ float d_damp1[NX];              // 1-D damp profile (x == y)
__device__ float4 d_slT[2*NBLK*NSLOT];     // [parity][blk][slot]: top-row Ez, tag-fused
__device__ float4 d_slB[2*NBLK*NSLOT];     // bottom-row Ez, tag-fused

// GPU-scope relaxed 16B exchange ops (stay in L2)
__device__ __forceinline__ float4 ld_gpu_v4(const float4* p) {
    float4 v;
    asm volatile("ld.relaxed.gpu.global.v4.f32 {%0,%1,%2,%3}, [%4];"
                 : "=f"(v.x), "=f"(v.y), "=f"(v.z), "=f"(v.w) : "l"(p) : "memory");
    return v;
}
__device__ __forceinline__ void st_gpu_v4(float4* p, float4 v) {
    asm volatile("st.relaxed.gpu.global.v4.f32 [%0], {%1,%2,%3,%4};"
                 :: "l"(p), "f"(v.x), "f"(v.y), "f"(v.z), "f"(v.w) : "memory");
}

// ---- packed f32x2 helpers ----
__device__ __forceinline__ u64 pk(float a, float b) {
    u64 r; asm("mov.b64 %0, {%1, %2};" : "=l"(r) : "f"(a), "f"(b)); return r;
}
__device__ __forceinline__ void upk(u64 v, float& a, float& b) {
    asm("mov.b64 {%0, %1}, %2;" : "=f"(a), "=f"(b) : "l"(v));
}
__device__ __forceinline__ u64 f2sub(u64 a, u64 b) {
    u64 d; asm("sub.rn.f32x2 %0, %1, %2;" : "=l"(d) : "l"(a), "l"(b)); return d;
}
__device__ __forceinline__ u64 f2mul(u64 a, u64 b) {
    u64 d; asm("mul.rn.f32x2 %0, %1, %2;" : "=l"(d) : "l"(a), "l"(b)); return d;
}
__device__ __forceinline__ u64 f2fma(u64 a, u64 b, u64 c) {
    u64 d; asm("fma.rn.f32x2 %0, %1, %2, %3;" : "=l"(d) : "l"(a), "l"(b), "l"(c)); return d;
}

// ---------------- setup: eps, damp, zero slot buffers ----------------
__global__ void setup_kernel(const float* __restrict__ radius) {
    int idx = blockIdx.x * blockDim.x + threadIdx.x;
    if (idx < 2*NBLK*NSLOT) {
        d_slT[idx] = make_float4(0.f, 0.f, 0.f, 0.f);   // tag 0 == "step 0 published", Ez=0
        d_slB[idx] = make_float4(0.f, 0.f, 0.f, 0.f);
    }
    if (idx < NX) {
        float v = 1.0f;
        if (idx < 10) {
            float rr = (10 - idx - 0.5f) * 0.1f;
            v = expf(-0.5f * rr * rr * rr);
        } else if (idx >= NX - 10) {
            float rr = (10 - (NX - 1 - idx) - 0.5f) * 0.1f;
            v = expf(-0.5f * rr * rr * rr);
        }
        d_damp1[idx] = v;
    }
    if (idx >= NC) return;
    int i = idx / NY;
    int j = idx - i * NY;
    int p   = (j + 10) / 80 - 1;
    int off = (j + 10) - 80 * (p + 1);
    bool inport = (p >= 0 && p < 4 && off < 20);
    float eps = 1.0f;
    if ((i < SRC_I || i >= DET_I) && inport) eps = 2.8f;
    if (i >= 80 && i < 320 && j >= 80 && j < 320) {
        int X = i - 80, Y = j - 80;
        int a = X / 30, b = Y / 30;
        float r = radius[a * 8 + b];
        if (r < 0.3f) r = 0.0f;
        float dx = (float)(X - (15 + 30 * a));
        float dy = (float)(Y - (15 + 30 * b));
        eps = (dx * dx + dy * dy <= r * r) ? 1.0f : 2.8f;
    }
    d_ie[idx] = 0.5f / eps;
}

// ---------- persistent strip kernel: ILP-2 (8 cols/thread), register halos, prefetched exchange ----------
__global__ void __launch_bounds__(TPB, 1)
fdtd_kernel(const float* __restrict__ phases, float* __restrict__ out)
{
    __shared__ __align__(16) float sEz[2*MAXH*NY];   // parity double-buffered Ez

    const int bk    = blockIdx.x;
    const int batch = bk / NSTRIP;
    const int s     = bk - batch * NSTRIP;
    const int r0    = (s * NX) / NSTRIP;
    const int r1    = ((s + 1) * NX) / NSTRIP;
    const int h     = r1 - r0;
    const bool hasA = (s > 0);
    const bool hasB = (s < NSTRIP - 1);
    const int tid   = threadIdx.x;
    const int bkA   = hasA ? bk - 1 : bk;
    const int bkB   = hasB ? bk + 1 : bk;

    // 50 threads per row (8 cols each); boundary rows to highest warps
    const int  li   = tid / 50;
    const int  jq   = tid - li * 50;
    const bool act  = (li < h);
    int l;
    if (li == h - 2)      l = 0;
    else if (li == h - 1) l = h - 1;
    else                  l = li + 1;
    if (!act) l = 0;

    const int  i    = r0 + l;
    const int  jo   = jq * 8;
    const int  o    = l * NY + jo;
    const bool topT = act && (l == 0);
    const bool botT = act && (l == h - 1);
    const bool spinA = topT && hasA;
    const bool spinB = botT && hasB;
    const bool upReg  = act && (l > 0);
    const bool dnReg  = act && (l < h - 1);
    const bool edgeTop = topT && !hasA;
    const bool edgeL   = (jq == 0);
    const bool lastT   = (jq == 49);

    for (int x = tid; x < 2*MAXH*NY; x += TPB) sEz[x] = 0.f;

    // tag-fused slot pointers: 4 slots of 2 cols per thread (parity offset added per step)
    const int si = jq * 4;
    const float4* plA = d_slB + bkA*NSLOT + si;
    const float4* plB = d_slT + bkB*NSLOT + si;
    float4*       psT = d_slT + bk*NSLOT + si;
    float4*       psB = d_slB + bk*NSLOT + si;

    // packed state: two quads A (cols 0-3) and B (cols 4-7)
    u64 ezA01=0, ezA23=0, ezB01=0, ezB23=0;
    u64 hxA01=0, hxA23=0, hxB01=0, hxB23=0;
    u64 hyA01=0, hyA23=0, hyB01=0, hyB23=0;
    u64 hUA01=0, hUA23=0, hUB01=0, hUB23=0;
    float hxW = 0.f;
    u64 dA01=0, dA23=0, dB01=0, dB23=0;            // damp
    u64 kA01=0, kA23=0, kB01=0, kB23=0;            // iek
    u64 c_rU2 = 0;
    const u64 c_half  = pk(0.5f, 0.5f);
    const u64 c_nhalf = pk(-0.5f, -0.5f);
    float rLdmp = 0.f;
    float4 SsA={0,0,0,0}, ScA={0,0,0,0}, SsB={0,0,0,0}, ScB={0,0,0,0};
    bool hasSrc = false, hasDet = false;

    if (act) {
        float di = d_damp1[i];
        dA01 = pk(di*d_damp1[jo],   di*d_damp1[jo+1]);
        dA23 = pk(di*d_damp1[jo+2], di*d_damp1[jo+3]);
        dB01 = pk(di*d_damp1[jo+4], di*d_damp1[jo+5]);
        dB23 = pk(di*d_damp1[jo+6], di*d_damp1[jo+7]);
        float4 ia = *(const float4*)&d_ie[i * NY + jo];
        float4 ib = *(const float4*)&d_ie[i * NY + jo + 4];
        kA01 = pk(ia.x, ia.y); kA23 = pk(ia.z, ia.w);
        kB01 = pk(ib.x, ib.y); kB23 = pk(ib.z, ib.w);
        float rU = (i > 0) ? d_damp1[i - 1] / di : 1.f;
        c_rU2 = pk(rU, rU);
        float rL = (jo > 0) ? d_damp1[jo - 1] / d_damp1[jo] : 1.f;
        rLdmp = rL * (di * d_damp1[jo]);
        if (i == SRC_I || i == DET_I) {
            float* sa = &SsA.x; float* ca = &ScA.x;
            float* sb = &SsB.x; float* cb = &ScB.x;
            #pragma unroll
            for (int c = 0; c < 8; ++c) {
                int j = jo + c;
                int p = (j + 10) / 80 - 1;
                int o2 = (j + 10) - 80 * (p + 1);
                bool inport = (p >= 0 && p < 4 && o2 < 20);
                if (inport && i == SRC_I) {
                    float ps = PI_F * phases[batch * 4 + p];
                    if (c < 4) { sa[c] = sinf(ps); ca[c] = cosf(ps); }
                    else       { sb[c-4] = sinf(ps); cb[c-4] = cosf(ps); }
                    hasSrc = true;
                }
                if (inport && i == DET_I) hasDet = true;
            }
        }
    }
    const float W  = (float)(2.0 * 3.14159265358979323846 * (12.5 / 1550.0));
    const float cW = cosf(W), sW = sinf(W);
    __syncthreads();

    // prime the prefetch pipeline (parity 0; init tags==0 valid for step 1)
    float4 a0={0,0,0,0}, a1={0,0,0,0}, a2={0,0,0,0}, a3={0,0,0,0};
    float4 b0={0,0,0,0}, b1={0,0,0,0}, b2={0,0,0,0}, b3={0,0,0,0};
    if (spinA) { a0=ld_gpu_v4(plA); a1=ld_gpu_v4(plA+1); a2=ld_gpu_v4(plA+2); a3=ld_gpu_v4(plA+3); }
    if (spinB) { b0=ld_gpu_v4(plB); b1=ld_gpu_v4(plB+1); b2=ld_gpu_v4(plB+2); b3=ld_gpu_v4(plB+3); }

    float tf1 = 0.f, tagf = 1.f;
    for (unsigned t = 1; t <= STEPS; ++t) {
        const int qo = (int)((t - 1) & 1u) * (NBLK*NSLOT);
        const int po = (int)(t & 1u) * (NBLK*NSLOT);
        const float* bufQ = sEz + (int)((t - 1) & 1u) * (MAXH*NY);
        float*       bufP = sEz + (int)(t & 1u) * (MAXH*NY);

        // ---- unpack own Ez(t-1) ----
        float eA0,eA1,eA2,eA3, eB0,eB1,eB2,eB3;
        upk(ezA01,eA0,eA1); upk(ezA23,eA2,eA3);
        upk(ezB01,eB0,eB1); upk(ezB23,eB2,eB3);
        float ezL = eA0, ezE = eB3;
        u64 eUA01=ezA01, eUA23=ezA23, eUB01=ezB01, eUB23=ezB23;
        u64 eDA01=ezA01, eDA23=ezA23, eDB01=ezB01, eDB23=ezB23;
        if (act) {
            if (!edgeL) ezL = bufQ[o - 1];
            if (!lastT) ezE = bufQ[o + 8];
            if (upReg) {
                ulonglong2 u = *(const ulonglong2*)&bufQ[o - NY];
                ulonglong2 v = *(const ulonglong2*)&bufQ[o - NY + 4];
                eUA01=u.x; eUA23=u.y; eUB01=v.x; eUB23=v.y;
            }
            if (dnReg) {
                ulonglong2 u = *(const ulonglong2*)&bufQ[o + NY];
                ulonglong2 v = *(const ulonglong2*)&bufQ[o + NY + 4];
                eDA01=u.x; eDA23=u.y; eDB01=v.x; eDB23=v.y;
            }
        }
        // ---- consume prefetched slots; on stale tag fall back to poll loop ----
        if (spinA) {
            while (a0.x<tf1 || a0.w<tf1 || a1.x<tf1 || a1.w<tf1 ||
                   a2.x<tf1 || a2.w<tf1 || a3.x<tf1 || a3.w<tf1) {
                a0=ld_gpu_v4(plA+qo); a1=ld_gpu_v4(plA+qo+1);
                a2=ld_gpu_v4(plA+qo+2); a3=ld_gpu_v4(plA+qo+3);
            }
            eUA01 = pk(a0.y, a0.z); eUA23 = pk(a1.y, a1.z);
            eUB01 = pk(a2.y, a2.z); eUB23 = pk(a3.y, a3.z);
        }
        if (spinB) {
            while (b0.x<tf1 || b0.w<tf1 || b1.x<tf1 || b1.w<tf1 ||
                   b2.x<tf1 || b2.w<tf1 || b3.x<tf1 || b3.w<tf1) {
                b0=ld_gpu_v4(plB+qo); b1=ld_gpu_v4(plB+qo+1);
                b2=ld_gpu_v4(plB+qo+2); b3=ld_gpu_v4(plB+qo+3);
            }
            eDA01 = pk(b0.y, b0.z); eDA23 = pk(b1.y, b1.z);
            eDB01 = pk(b2.y, b2.z); eDB23 = pk(b3.y, b3.z);
        }

        if (act) {
            const u64 eRA01 = pk(eA1, eA2);
            const u64 eRA23 = pk(eA3, eB0);
            const u64 eRB01 = pk(eB1, eB2);
            const u64 eRB23 = pk(eB3, ezE);

            // ---- H phase (two independent quad chains; same rounding as scalar) ----
            hxA01 = f2mul(dA01, f2fma(c_nhalf, f2sub(eRA01, ezA01), hxA01));
            hxB01 = f2mul(dB01, f2fma(c_nhalf, f2sub(eRB01, ezB01), hxB01));
            hxA23 = f2mul(dA23, f2fma(c_nhalf, f2sub(eRA23, ezA23), hxA23));
            hxB23 = f2mul(dB23, f2fma(c_nhalf, f2sub(eRB23, ezB23), hxB23));
            hyA01 = f2mul(dA01, f2fma(c_half, f2sub(eDA01, ezA01), hyA01));
            hyB01 = f2mul(dB01, f2fma(c_half, f2sub(eDB01, ezB01), hyB01));
            hyA23 = f2mul(dA23, f2fma(c_half, f2sub(eDA23, ezA23), hyA23));
            hyB23 = f2mul(dB23, f2fma(c_half, f2sub(eDB23, ezB23), hyB23));
            hUA01 = f2mul(c_rU2, f2mul(dA01, f2fma(c_half, f2sub(ezA01, eUA01), hUA01)));
            hUB01 = f2mul(c_rU2, f2mul(dB01, f2fma(c_half, f2sub(ezB01, eUB01), hUB01)));
            hUA23 = f2mul(c_rU2, f2mul(dA23, f2fma(c_half, f2sub(ezA23, eUA23), hUA23)));
            hUB23 = f2mul(c_rU2, f2mul(dB23, f2fma(c_half, f2sub(ezB23, eUB23), hUB23)));
            hxW = rLdmp * __fmaf_rn(-0.5f, eA0 - ezL, hxW);

            // ---- E phase: all registers ----
            float hA0,hA1,hA2,hA3, hB0,hB1,hB2,hB3;
            upk(hxA01,hA0,hA1); upk(hxA23,hA2,hA3);
            upk(hxB01,hB0,hB1); upk(hxB23,hB2,hB3);
            const u64 hLA01 = pk(edgeL ? hA0 : hxW, hA0);
            const u64 hLA23 = pk(hA1, hA2);
            const u64 hLB01 = pk(hA3, hB0);
            const u64 hLB23 = pk(hB1, hB2);
            const u64 hUeA01 = edgeTop ? hyA01 : hUA01;
            const u64 hUeA23 = edgeTop ? hyA23 : hUA23;
            const u64 hUeB01 = edgeTop ? hyB01 : hUB01;
            const u64 hUeB23 = edgeTop ? hyB23 : hUB23;
            u64 cA01 = f2sub(f2sub(hyA01, hUeA01), f2sub(hxA01, hLA01));
            u64 cB01 = f2sub(f2sub(hyB01, hUeB01), f2sub(hxB01, hLB01));
            u64 cA23 = f2sub(f2sub(hyA23, hUeA23), f2sub(hxA23, hLA23));
            u64 cB23 = f2sub(f2sub(hyB23, hUeB23), f2sub(hxB23, hLB23));
            ezA01 = f2mul(dA01, f2fma(kA01, cA01, ezA01));
            ezB01 = f2mul(dB01, f2fma(kB01, cB01, ezB01));
            ezA23 = f2mul(dA23, f2fma(kA23, cA23, ezA23));
            ezB23 = f2mul(dB23, f2fma(kB23, cB23, ezB23));

            if (hasSrc) {
                float g0,g1,g2,g3, g4,g5,g6,g7;
                upk(ezA01,g0,g1); upk(ezA23,g2,g3);
                upk(ezB01,g4,g5); upk(ezB23,g6,g7);
                g0 += SsA.x; g1 += SsA.y; g2 += SsA.z; g3 += SsA.w;
                g4 += SsB.x; g5 += SsB.y; g6 += SsB.z; g7 += SsB.w;
                ezA01 = pk(g0,g1); ezA23 = pk(g2,g3);
                ezB01 = pk(g4,g5); ezB23 = pk(g6,g7);
                float ns, nc;
                ns = SsA.x*cW + ScA.x*sW; nc = ScA.x*cW - SsA.x*sW; SsA.x = ns; ScA.x = nc;
                ns = SsA.y*cW + ScA.y*sW; nc = ScA.y*cW - SsA.y*sW; SsA.y = ns; ScA.y = nc;
                ns = SsA.z*cW + ScA.z*sW; nc = ScA.z*cW - SsA.z*sW; SsA.z = ns; ScA.z = nc;
                ns = SsA.w*cW + ScA.w*sW; nc = ScA.w*cW - SsA.w*sW; SsA.w = ns; ScA.w = nc;
                ns = SsB.x*cW + ScB.x*sW; nc = ScB.x*cW - SsB.x*sW; SsB.x = ns; ScB.x = nc;
                ns = SsB.y*cW + ScB.y*sW; nc = ScB.y*cW - SsB.y*sW; SsB.y = ns; ScB.y = nc;
                ns = SsB.z*cW + ScB.z*sW; nc = ScB.z*cW - SsB.z*sW; SsB.z = ns; ScB.z = nc;
                ns = SsB.w*cW + ScB.w*sW; nc = ScB.w*cW - SsB.w*sW; SsB.w = ns; ScB.w = nc;
            }

            // ---- publish boundary slots ASAP (protocol covers WAR on parity slots) ----
            if (topT | botT) {
                float p0,p1,p2,p3, p4,p5,p6,p7;
                upk(ezA01,p0,p1); upk(ezA23,p2,p3);
                upk(ezB01,p4,p5); upk(ezB23,p6,p7);
                if (topT) {
                    st_gpu_v4(psT+po,   make_float4(tagf,p0,p1,tagf));
                    st_gpu_v4(psT+po+1, make_float4(tagf,p2,p3,tagf));
                    st_gpu_v4(psT+po+2, make_float4(tagf,p4,p5,tagf));
                    st_gpu_v4(psT+po+3, make_float4(tagf,p6,p7,tagf));
                }
                if (botT) {
                    st_gpu_v4(psB+po,   make_float4(tagf,p0,p1,tagf));
                    st_gpu_v4(psB+po+1, make_float4(tagf,p2,p3,tagf));
                    st_gpu_v4(psB+po+2, make_float4(tagf,p4,p5,tagf));
                    st_gpu_v4(psB+po+3, make_float4(tagf,p6,p7,tagf));
                }
            }
            ulonglong2 s1; s1.x = ezA01; s1.y = ezA23;
            ulonglong2 s2; s2.x = ezB01; s2.y = ezB23;
            *(ulonglong2*)&bufP[o] = s1;
            *(ulonglong2*)&bufP[o + 4] = s2;
        }

        // ---- prefetch next step's halo slots (parity po); latency hidden by the bar ----
        if (spinA) { a0=ld_gpu_v4(plA+po); a1=ld_gpu_v4(plA+po+1); a2=ld_gpu_v4(plA+po+2); a3=ld_gpu_v4(plA+po+3); }
        if (spinB) { b0=ld_gpu_v4(plB+po); b1=ld_gpu_v4(plB+po+1); b2=ld_gpu_v4(plB+po+2); b3=ld_gpu_v4(plB+po+3); }

        tf1 += 1.f; tagf += 1.f;
        __syncthreads();
    }

    // ---- detector: final Ez at row 370 lives in registers ----
    if (hasDet) {
        float e0,e1,e2,e3,e4,e5,e6,e7;
        upk(ezA01,e0,e1); upk(ezA23,e2,e3);
        upk(ezB01,e4,e5); upk(ezB23,e6,e7);
        float ec[8] = {e0,e1,e2,e3,e4,e5,e6,e7};
        #pragma unroll
        for (int c = 0; c < 8; ++c) {
            int j = jo + c;
            int p = (j + 10) / 80 - 1;
            int o2 = (j + 10) - 80 * (p + 1);
            if (p >= 0 && p < 4 && o2 < 20)
                out[batch * 80 + p * 20 + o2] = ec[c];
        }
    }
}

extern "C" void kernel_launch(void* const* d_in, const int* in_sizes, int n_in,
                              void* d_out, int out_size) {
    const float* phases = (const float*)d_in[0];   // (2,4)
    const float* radius = (const float*)d_in[1];   // (8,8)
    float* out = (float*)d_out;                    // (2,4,20)
    setup_kernel<<<(NC + 255) / 256, 256>>>(radius);
    fdtd_kernel<<<NBLK, TPB>>>(phases, out);
}